// round 2
// baseline (speedup 1.0000x reference)
#include <cuda_runtime.h>
#include <cuda_bf16.h>
#include <stdint.h>
#include <math.h>

// Problem constants (fixed by the dataset)
#define B_    256
#define D_    2048
#define N_    65536
#define C_    8192
#define TEMP_ 0.05f

// GEMM tiling
#define BM 256
#define BN 128
#define BK 32
#define BKP 40                  // padded K stride (bf16 elems) -> conflict-free frag loads
#define KT (D_ / BK)            // 64 k-iterations
#define NTHREADS 512
#define A_TILE (BM * BKP)
#define B_TILE (BN * BKP)
#define CTP 129                 // epilogue smem row stride (conflict-free walk)
#define GEMM_SMEM_BYTES (BM * CTP * 4)   // 132096 > 2*(A_TILE+B_TILE)*2 = 61440

// ---------------- device scratch (no allocations allowed) ----------------
__device__ float          g_S[B_ * C_];       // [b][c] raw segment sums of sims
__device__ float          g_diag[B_];          // sum of sims^2 over target segment
__device__ int            g_counts[C_];
__device__ int            g_offsets[C_];
__device__ int            g_cursor[C_];
__device__ int            g_perm[N_];          // permuted column j -> original n
__device__ int            g_clab[N_];          // cluster of permuted column j
__device__ int            g_targets[B_];
__device__ __nv_bfloat16  g_Abf[B_ * D_];      // inputs in bf16
__device__ float          g_lossb[B_];

// ---------------- small helpers ----------------
__device__ __forceinline__ void cp_async16(void* sptr, const void* gptr) {
    uint32_t s = (uint32_t)__cvta_generic_to_shared(sptr);
    asm volatile("cp.async.cg.shared.global [%0], [%1], 16;\n" :: "r"(s), "l"(gptr));
}
#define CP_COMMIT() asm volatile("cp.async.commit_group;\n" ::: "memory")
#define CP_WAIT0()  asm volatile("cp.async.wait_group 0;\n" ::: "memory")

__device__ __forceinline__ void mma16816(float* c,
                                         uint32_t a0, uint32_t a1, uint32_t a2, uint32_t a3,
                                         uint32_t b0, uint32_t b1) {
    asm volatile(
        "mma.sync.aligned.m16n8k16.row.col.f32.bf16.bf16.f32 "
        "{%0,%1,%2,%3}, {%4,%5,%6,%7}, {%8,%9}, {%0,%1,%2,%3};\n"
        : "+f"(c[0]), "+f"(c[1]), "+f"(c[2]), "+f"(c[3])
        : "r"(a0), "r"(a1), "r"(a2), "r"(a3), "r"(b0), "r"(b1));
}

__device__ __forceinline__ void store_b_frag(__nv_bfloat16* dst, int bn, int bq,
                                             float4 f0, float4 f1) {
    __nv_bfloat162 h0 = __floats2bfloat162_rn(f0.x, f0.y);
    __nv_bfloat162 h1 = __floats2bfloat162_rn(f0.z, f0.w);
    __nv_bfloat162 h2 = __floats2bfloat162_rn(f1.x, f1.y);
    __nv_bfloat162 h3 = __floats2bfloat162_rn(f1.z, f1.w);
    uint4 u;
    u.x = *(uint32_t*)&h0; u.y = *(uint32_t*)&h1;
    u.z = *(uint32_t*)&h2; u.w = *(uint32_t*)&h3;
    *(uint4*)(dst + bn * BKP + bq * 8) = u;
}

// ---------------- setup kernels ----------------
__global__ void k_zero() {
    int i = blockIdx.x * blockDim.x + threadIdx.x;
    int stride = gridDim.x * blockDim.x;
    for (int j = i; j < B_ * C_; j += stride) g_S[j] = 0.f;
    if (i < C_) { g_counts[i] = 0; g_cursor[i] = 0; }
    if (i < B_) g_diag[i] = 0.f;
}

__global__ void k_count(const int* __restrict__ labels,
                        const int* __restrict__ indexes) {
    int n = blockIdx.x * blockDim.x + threadIdx.x;
    if (n < N_) atomicAdd(&g_counts[labels[n]], 1);
    if (n < B_) g_targets[n] = labels[indexes[n]];
}

__global__ void k_scan() {   // exclusive prefix sum over C_=8192 counts, 1 block x 256
    __shared__ int part[256];
    int t = threadIdx.x;
    int base = t * 32;
    int loc[32];
    int s = 0;
#pragma unroll
    for (int i = 0; i < 32; i++) { loc[i] = s; s += g_counts[base + i]; }
    part[t] = s;
    __syncthreads();
    int own = s;
    for (int off = 1; off < 256; off <<= 1) {
        int v = (t >= off) ? part[t - off] : 0;
        __syncthreads();
        part[t] += v;
        __syncthreads();
    }
    int excl = part[t] - own;
#pragma unroll
    for (int i = 0; i < 32; i++) g_offsets[base + i] = excl + loc[i];
}

__global__ void k_scatter(const int* __restrict__ labels) {
    int n = blockIdx.x * blockDim.x + threadIdx.x;
    if (n < N_) {
        int c = labels[n];
        int p = g_offsets[c] + atomicAdd(&g_cursor[c], 1);
        g_perm[p] = n;
        g_clab[p] = c;
    }
}

__global__ void k_conv(const float* __restrict__ inputs) {
    int i = blockIdx.x * blockDim.x + threadIdx.x;
    if (i < B_ * D_) g_Abf[i] = __float2bfloat16(inputs[i]);
}

// ---------------- fused GEMM + segmented reduction ----------------
__global__ void __launch_bounds__(NTHREADS) k_gemm(const float* __restrict__ features) {
    extern __shared__ char smem[];
    __nv_bfloat16* As = (__nv_bfloat16*)smem;       // [2][A_TILE]
    __nv_bfloat16* Bs = As + 2 * A_TILE;            // [2][B_TILE]
    __shared__ int s_perm[BN];
    __shared__ int s_clab[BN];

    int tid = threadIdx.x;
    int jb = blockIdx.x * BN;
    if (tid < BN) { s_perm[tid] = g_perm[jb + tid]; s_clab[tid] = g_clab[jb + tid]; }
    __syncthreads();

    int lane = tid & 31, w = tid >> 5;
    int wm = (w & 7) * 32;        // warp row base (8 warps along M)
    int wn = (w >> 3) * 64;       // warp col base (2 warps along N)
    int g = lane >> 2, tg = lane & 3;

    // staging roles
    int arow = tid >> 1, ahalf = tid & 1;                       // A: 2 threads / row
    const __nv_bfloat16* Ag = g_Abf + arow * D_ + ahalf * 16;
    int bn = tid >> 2, bq = tid & 3;                            // B: 4 threads / row
    const float* Bg = features + (size_t)s_perm[bn] * (size_t)D_ + bq * 8;

    float acc[2][8][4];
#pragma unroll
    for (int mi = 0; mi < 2; mi++)
#pragma unroll
        for (int ni = 0; ni < 8; ni++)
#pragma unroll
            for (int q = 0; q < 4; q++) acc[mi][ni][q] = 0.f;

    float4 f0, f1;
    // prologue: stage k-tile 0
    {
        __nv_bfloat16* Ad = As + arow * BKP + ahalf * 16;
        cp_async16(Ad, Ag);
        cp_async16(Ad + 8, Ag + 8);
        CP_COMMIT();
        f0 = *(const float4*)(Bg);
        f1 = *(const float4*)(Bg + 4);
        store_b_frag(Bs, bn, bq, f0, f1);
        CP_WAIT0();
    }
    __syncthreads();

    for (int kt = 0; kt < KT; ++kt) {
        int nxt = kt + 1;
        const __nv_bfloat16* Ab = As + (kt & 1) * A_TILE;
        const __nv_bfloat16* Bb = Bs + (kt & 1) * B_TILE;

        if (nxt < KT) {
            int k0 = nxt * BK;
            __nv_bfloat16* Ad = As + (nxt & 1) * A_TILE + arow * BKP + ahalf * 16;
            cp_async16(Ad, Ag + k0);
            cp_async16(Ad + 8, Ag + k0 + 8);
            CP_COMMIT();
            f0 = *(const float4*)(Bg + k0);
            f1 = *(const float4*)(Bg + k0 + 4);
        }

#pragma unroll
        for (int ks = 0; ks < 2; ks++) {
            int kk = ks * 16 + 2 * tg;
            uint32_t bF0[8], bF1[8];
#pragma unroll
            for (int ni = 0; ni < 8; ni++) {
                int n = wn + ni * 8 + g;
                bF0[ni] = *(const uint32_t*)(Bb + n * BKP + kk);
                bF1[ni] = *(const uint32_t*)(Bb + n * BKP + kk + 8);
            }
#pragma unroll
            for (int mi = 0; mi < 2; mi++) {
                int r = wm + mi * 16 + g;
                uint32_t a0 = *(const uint32_t*)(Ab + r * BKP + kk);
                uint32_t a1 = *(const uint32_t*)(Ab + (r + 8) * BKP + kk);
                uint32_t a2 = *(const uint32_t*)(Ab + r * BKP + kk + 8);
                uint32_t a3 = *(const uint32_t*)(Ab + (r + 8) * BKP + kk + 8);
#pragma unroll
                for (int ni = 0; ni < 8; ni++)
                    mma16816(acc[mi][ni], a0, a1, a2, a3, bF0[ni], bF1[ni]);
            }
        }

        if (nxt < KT) store_b_frag(Bs + (nxt & 1) * B_TILE, bn, bq, f0, f1);
        CP_WAIT0();
        __syncthreads();
    }

    // ---- epilogue: dump sims tile to smem, run-length reduce per label segment ----
    float* Ct = (float*)smem;   // [BM][CTP], reuses operand smem (all reads done)
#pragma unroll
    for (int mi = 0; mi < 2; mi++) {
        int r = wm + mi * 16 + g;
#pragma unroll
        for (int ni = 0; ni < 8; ni++) {
            int c = wn + ni * 8 + 2 * tg;
            Ct[r * CTP + c]           = acc[mi][ni][0];
            Ct[r * CTP + c + 1]       = acc[mi][ni][1];
            Ct[(r + 8) * CTP + c]     = acc[mi][ni][2];
            Ct[(r + 8) * CTP + c + 1] = acc[mi][ni][3];
        }
    }
    __syncthreads();

    int b = tid & 255;
    int half = tid >> 8;          // 2 threads per row, 64 cols each
    int tb = g_targets[b];
    const float* row = Ct + b * CTP + half * 64;
    const int* cl = s_clab + half * 64;
    float run = 0.f, run2 = 0.f;
    int cur = cl[0];
    for (int j = 0; j < 64; j++) {
        int c = cl[j];
        float v = row[j];
        if (c != cur) {
            atomicAdd(&g_S[b * C_ + cur], run);
            if (cur == tb) atomicAdd(&g_diag[b], run2);
            run = 0.f; run2 = 0.f; cur = c;
        }
        run += v;
        if (c == tb) run2 += v * v;
    }
    atomicAdd(&g_S[b * C_ + cur], run);
    if (cur == tb) atomicAdd(&g_diag[b], run2);
}

// ---------------- masked softmax + NLL ----------------
__global__ void k_softmax() {
    int b = blockIdx.x, t = threadIdx.x;
    int tb = g_targets[b];
    const float* Srow = g_S + b * C_;
    float dg = g_diag[b] * (1.f / TEMP_);
    __shared__ float s_et;
    __shared__ float red[256];
    float denom = 0.f;
    for (int c = t; c < C_; c += 256) {
        int cnt = g_counts[c];
        float e = 0.f;
        if (cnt > 0) {
            float sim = (c == tb) ? dg : (Srow[c] * (1.f / TEMP_) / (float)cnt);
            e = expf(sim);
            if (c == tb) s_et = e;   // exactly one thread hits this
        }
        denom += e;
    }
    red[t] = denom;
    __syncthreads();
    for (int o = 128; o > 0; o >>= 1) {
        if (t < o) red[t] += red[t + o];
        __syncthreads();
    }
    if (t == 0) {
        float p = s_et / (red[0] + 1e-6f) + 1e-6f;
        g_lossb[b] = -logf(p);
    }
}

__global__ void k_loss(float* __restrict__ out) {
    int t = threadIdx.x;
    __shared__ float red[256];
    red[t] = g_lossb[t];
    __syncthreads();
    for (int o = 128; o > 0; o >>= 1) {
        if (t < o) red[t] += red[t + o];
        __syncthreads();
    }
    if (t == 0) out[0] = red[0] / (float)B_;
}

// ---------------- launch ----------------
extern "C" void kernel_launch(void* const* d_in, const int* in_sizes, int n_in,
                              void* d_out, int out_size) {
    const float* inputs   = (const float*)d_in[0];
    const int*   indexes  = (const int*)d_in[1];
    const float* features = (const float*)d_in[2];
    const int*   labels   = (const int*)d_in[3];
    float*       out      = (float*)d_out;
    (void)in_sizes; (void)n_in; (void)out_size;

    cudaFuncSetAttribute(k_gemm, cudaFuncAttributeMaxDynamicSharedMemorySize,
                         GEMM_SMEM_BYTES);

    k_zero<<<4096, 256>>>();
    k_count<<<N_ / 256, 256>>>(labels, indexes);
    k_scan<<<1, 256>>>();
    k_scatter<<<N_ / 256, 256>>>(labels);
    k_conv<<<(B_ * D_ + 255) / 256, 256>>>(inputs);
    k_gemm<<<N_ / BN, NTHREADS, GEMM_SMEM_BYTES>>>(features);
    k_softmax<<<B_, 256>>>();
    k_loss<<<1, 256>>>(out);
}

// round 4
// speedup vs baseline: 1.1293x; 1.1293x over previous
#include <cuda_runtime.h>
#include <cuda_bf16.h>
#include <stdint.h>
#include <math.h>

// ---------------- problem constants ----------------
#define B_    256
#define D_    2048
#define N_    65536
#define C_    8192
#define TEMP_ 0.05f

// ---------------- GEMM tiling ----------------
#define BM 256
#define BN 128
#define BK 32
#define BKP 40                    // padded row stride (bf16 elems): 80 B, conflict-free
#define KT (D_ / BK)              // 64
#define NTHREADS 512
#define A_TILE_E (BM * BKP)       // 10240 elems / stage
#define B_TILE_E (BN * BKP)       // 5120 elems / stage
#define CTP 129
#define SMEM_BYTES (128 * CTP * 4)   // 66048 B; operands need 61440 -> union fits

// ---------------- device scratch ----------------
__device__ float          g_S[B_ * C_];
__device__ float          g_diag[B_];
__device__ int            g_counts[C_];
__device__ int            g_offsets[C_];
__device__ int            g_cursor[C_];
__device__ int            g_perm[N_];
__device__ int            g_clab[N_];
__device__ int            g_targets[B_];
__device__ __nv_bfloat16  g_Abf[B_ * D_];
__device__ float          g_lossb[B_];

// ---------------- helpers ----------------
__device__ __forceinline__ uint32_t smem_u32(const void* p) {
    uint32_t a;
    asm("{ .reg .u64 t; cvta.to.shared.u64 t, %1; cvt.u32.u64 %0, t; }" : "=r"(a) : "l"(p));
    return a;
}
__device__ __forceinline__ void cp_async16(uint32_t sdst, const void* g) {
    asm volatile("cp.async.cg.shared.global [%0], [%1], 16;\n" :: "r"(sdst), "l"(g));
}
#define CP_COMMIT() asm volatile("cp.async.commit_group;\n" ::: "memory")
#define CP_WAIT0()  asm volatile("cp.async.wait_group 0;\n" ::: "memory")

__device__ __forceinline__ void ldsm_x4(uint32_t& r0, uint32_t& r1, uint32_t& r2, uint32_t& r3,
                                        uint32_t addr) {
    asm volatile("ldmatrix.sync.aligned.m8n8.x4.shared.b16 {%0,%1,%2,%3}, [%4];"
                 : "=r"(r0), "=r"(r1), "=r"(r2), "=r"(r3) : "r"(addr));
}
__device__ __forceinline__ void mma16816(float* c,
                                         uint32_t a0, uint32_t a1, uint32_t a2, uint32_t a3,
                                         uint32_t b0, uint32_t b1) {
    asm volatile(
        "mma.sync.aligned.m16n8k16.row.col.f32.bf16.bf16.f32 "
        "{%0,%1,%2,%3}, {%4,%5,%6,%7}, {%8,%9}, {%0,%1,%2,%3};\n"
        : "+f"(c[0]), "+f"(c[1]), "+f"(c[2]), "+f"(c[3])
        : "r"(a0), "r"(a1), "r"(a2), "r"(a3), "r"(b0), "r"(b1));
}
__device__ __forceinline__ void store_b_frag(__nv_bfloat16* dst, int bn, int bq,
                                             float4 f0, float4 f1) {
    __nv_bfloat162 h0 = __floats2bfloat162_rn(f0.x, f0.y);
    __nv_bfloat162 h1 = __floats2bfloat162_rn(f0.z, f0.w);
    __nv_bfloat162 h2 = __floats2bfloat162_rn(f1.x, f1.y);
    __nv_bfloat162 h3 = __floats2bfloat162_rn(f1.z, f1.w);
    uint4 u;
    u.x = *(uint32_t*)&h0; u.y = *(uint32_t*)&h1;
    u.z = *(uint32_t*)&h2; u.w = *(uint32_t*)&h3;
    *(uint4*)(dst + bn * BKP + bq * 8) = u;
}

// ---------------- setup kernels ----------------
__global__ void k_zero() {
    int i = blockIdx.x * blockDim.x + threadIdx.x;
    int stride = gridDim.x * blockDim.x;
    for (int j = i; j < B_ * C_; j += stride) g_S[j] = 0.f;
    if (i < C_) { g_counts[i] = 0; g_cursor[i] = 0; }
    if (i < B_) g_diag[i] = 0.f;
}
__global__ void k_count(const int* __restrict__ labels, const int* __restrict__ indexes) {
    int n = blockIdx.x * blockDim.x + threadIdx.x;
    if (n < N_) atomicAdd(&g_counts[labels[n]], 1);
    if (n < B_) g_targets[n] = labels[indexes[n]];
}
__global__ void k_scan() {
    __shared__ int part[256];
    int t = threadIdx.x;
    int base = t * 32;
    int loc[32];
    int s = 0;
#pragma unroll
    for (int i = 0; i < 32; i++) { loc[i] = s; s += g_counts[base + i]; }
    part[t] = s;
    __syncthreads();
    int own = s;
    for (int off = 1; off < 256; off <<= 1) {
        int v = (t >= off) ? part[t - off] : 0;
        __syncthreads();
        part[t] += v;
        __syncthreads();
    }
    int excl = part[t] - own;
#pragma unroll
    for (int i = 0; i < 32; i++) g_offsets[base + i] = excl + loc[i];
}
__global__ void k_scatter(const int* __restrict__ labels) {
    int n = blockIdx.x * blockDim.x + threadIdx.x;
    if (n < N_) {
        int c = labels[n];
        int p = g_offsets[c] + atomicAdd(&g_cursor[c], 1);
        g_perm[p] = n;
        g_clab[p] = c;
    }
}
__global__ void k_conv(const float* __restrict__ inputs) {
    int i = blockIdx.x * blockDim.x + threadIdx.x;
    if (i < B_ * D_) g_Abf[i] = __float2bfloat16(inputs[i]);
}

// ---------------- GEMM + fused segmented reduction ----------------
__global__ void __launch_bounds__(NTHREADS, 1) k_gemm(const float* __restrict__ features) {
    extern __shared__ char smem[];
    __nv_bfloat16* As = (__nv_bfloat16*)smem;          // 2 stages x A_TILE_E
    __nv_bfloat16* Bs = As + 2 * A_TILE_E;             // 2 stages x B_TILE_E
    __shared__ int s_perm[BN];
    __shared__ int s_clab[BN];

    int tid = threadIdx.x;
    int jb = blockIdx.x * BN;
    if (tid < BN) { s_perm[tid] = g_perm[jb + tid]; s_clab[tid] = g_clab[jb + tid]; }
    __syncthreads();

    int lane = tid & 31, w = tid >> 5;
    int wm = (w & 7) * 32;       // 8 warps along M
    int wn = (w >> 3) * 64;      // 2 warps along N
    int g = lane >> 2, tg = lane & 3;

    uint32_t sbA = smem_u32(As);
    uint32_t sbB = smem_u32(Bs);
    // per-lane ldmatrix base addresses (bytes)
    int rowA = wm + (lane & 15);
    int colA = (lane & 16) ? 8 : 0;
    uint32_t adA = sbA + (uint32_t)(rowA * BKP + colA) * 2;     // + mi*16*BKP*2 + ks*32
    int rowB = wn + (lane & 7) + ((lane & 16) ? 8 : 0);
    int colB = (lane & 8) ? 8 : 0;
    uint32_t adB = sbB + (uint32_t)(rowB * BKP + colB) * 2;     // + nb*16*BKP*2 + ks*32

    // staging roles
    int arow = tid >> 1, ahalf = tid & 1;
    const __nv_bfloat16* Ag = g_Abf + (size_t)arow * D_ + ahalf * 16;
    uint32_t adStA = sbA + (uint32_t)(arow * BKP + ahalf * 16) * 2;
    int bn = tid >> 2, bq = tid & 3;
    const float* Bg = features + (size_t)s_perm[bn] * (size_t)D_ + bq * 8;

    float acc[2][8][4];
#pragma unroll
    for (int mi = 0; mi < 2; mi++)
#pragma unroll
        for (int ni = 0; ni < 8; ni++)
#pragma unroll
            for (int q = 0; q < 4; q++) acc[mi][ni][q] = 0.f;

    float4 f0, f1;
    {   // prologue: stage k-tile 0
        cp_async16(adStA, Ag);
        cp_async16(adStA + 16, Ag + 8);
        CP_COMMIT();
        f0 = *(const float4*)(Bg);
        f1 = *(const float4*)(Bg + 4);
        store_b_frag(Bs, bn, bq, f0, f1);
        CP_WAIT0();
    }
    __syncthreads();

    for (int kt = 0; kt < KT; ++kt) {
        int nxt = kt + 1;
        uint32_t aA = adA + (kt & 1) * (A_TILE_E * 2);
        uint32_t aB = adB + (kt & 1) * (B_TILE_E * 2);

        if (nxt < KT) {
            int k0 = nxt * BK;
            uint32_t ad = adStA + (nxt & 1) * (A_TILE_E * 2);
            cp_async16(ad, Ag + k0);
            cp_async16(ad + 16, Ag + k0 + 8);
            CP_COMMIT();
            f0 = *(const float4*)(Bg + k0);
            f1 = *(const float4*)(Bg + k0 + 4);
        }

#pragma unroll
        for (int ks = 0; ks < 2; ks++) {
            uint32_t bF0[8], bF1[8];
#pragma unroll
            for (int nb = 0; nb < 4; nb++)
                ldsm_x4(bF0[2 * nb], bF1[2 * nb], bF0[2 * nb + 1], bF1[2 * nb + 1],
                        aB + nb * (16 * BKP * 2) + ks * 32);
#pragma unroll
            for (int mi = 0; mi < 2; mi++) {
                uint32_t a0, a1, a2, a3;
                ldsm_x4(a0, a1, a2, a3, aA + mi * (16 * BKP * 2) + ks * 32);
#pragma unroll
                for (int ni = 0; ni < 8; ni++)
                    mma16816(acc[mi][ni], a0, a1, a2, a3, bF0[ni], bF1[ni]);
            }
        }

        if (nxt < KT) store_b_frag(Bs + (nxt & 1) * B_TILE_E, bn, bq, f0, f1);
        CP_WAIT0();
        __syncthreads();
    }

    // ---- epilogue: two 128-row halves through a 66 KB smem buffer ----
    float* Ct = (float*)smem;
    int erow = tid >> 2;          // 0..127
    int eq = tid & 3;             // col quarter (32 cols)
#pragma unroll
    for (int half = 0; half < 2; half++) {
        if ((wm >> 7) == half) {
            int r0 = wm - half * 128;
#pragma unroll
            for (int mi = 0; mi < 2; mi++) {
                int r = r0 + mi * 16 + g;
#pragma unroll
                for (int ni = 0; ni < 8; ni++) {
                    int c = wn + ni * 8 + 2 * tg;
                    Ct[r * CTP + c]           = acc[mi][ni][0];
                    Ct[r * CTP + c + 1]       = acc[mi][ni][1];
                    Ct[(r + 8) * CTP + c]     = acc[mi][ni][2];
                    Ct[(r + 8) * CTP + c + 1] = acc[mi][ni][3];
                }
            }
        }
        __syncthreads();

        int b = half * 128 + erow;
        int tb = g_targets[b];
        const float* row = Ct + erow * CTP + eq * 32;
        const int* cl = s_clab + eq * 32;
        float run = 0.f, run2 = 0.f;
        int cur = cl[0];
#pragma unroll 8
        for (int j = 0; j < 32; j++) {
            int c = cl[j];
            float v = row[j];
            if (c != cur) {
                atomicAdd(&g_S[b * C_ + cur], run);
                if (cur == tb) atomicAdd(&g_diag[b], run2);
                run = 0.f; run2 = 0.f; cur = c;
            }
            run += v;
            if (c == tb) run2 += v * v;
        }
        atomicAdd(&g_S[b * C_ + cur], run);
        if (cur == tb) atomicAdd(&g_diag[b], run2);
        __syncthreads();
    }
}

// ---------------- masked softmax + NLL ----------------
__global__ void k_softmax() {
    int b = blockIdx.x, t = threadIdx.x;
    int tb = g_targets[b];
    const float* Srow = g_S + b * C_;
    float dg = g_diag[b] * (1.f / TEMP_);
    __shared__ float s_et;
    __shared__ float red[256];
    float denom = 0.f;
    for (int c = t; c < C_; c += 256) {
        int cnt = g_counts[c];
        float e = 0.f;
        if (cnt > 0) {
            float sim = (c == tb) ? dg : (Srow[c] * (1.f / TEMP_) / (float)cnt);
            e = expf(sim);
            if (c == tb) s_et = e;
        }
        denom += e;
    }
    red[t] = denom;
    __syncthreads();
    for (int o = 128; o > 0; o >>= 1) {
        if (t < o) red[t] += red[t + o];
        __syncthreads();
    }
    if (t == 0) {
        float p = s_et / (red[0] + 1e-6f) + 1e-6f;
        g_lossb[b] = -logf(p);
    }
}
__global__ void k_loss(float* __restrict__ out) {
    int t = threadIdx.x;
    __shared__ float red[256];
    red[t] = g_lossb[t];
    __syncthreads();
    for (int o = 128; o > 0; o >>= 1) {
        if (t < o) red[t] += red[t + o];
        __syncthreads();
    }
    if (t == 0) out[0] = red[0] / (float)B_;
}

// ---------------- launch ----------------
extern "C" void kernel_launch(void* const* d_in, const int* in_sizes, int n_in,
                              void* d_out, int out_size) {
    const float* inputs   = (const float*)d_in[0];
    const int*   indexes  = (const int*)d_in[1];
    const float* features = (const float*)d_in[2];
    const int*   labels   = (const int*)d_in[3];
    float*       out      = (float*)d_out;
    (void)in_sizes; (void)n_in; (void)out_size;

    cudaFuncSetAttribute(k_gemm, cudaFuncAttributeMaxDynamicSharedMemorySize, SMEM_BYTES);

    k_zero<<<4096, 256>>>();
    k_count<<<N_ / 256, 256>>>(labels, indexes);
    k_scan<<<1, 256>>>();
    k_scatter<<<N_ / 256, 256>>>(labels);
    k_conv<<<(B_ * D_ + 255) / 256, 256>>>(inputs);
    k_gemm<<<N_ / BN, NTHREADS, SMEM_BYTES>>>(features);
    k_softmax<<<B_, 256>>>();
    k_loss<<<1, 256>>>(out);
}